// round 1
// baseline (speedup 1.0000x reference)
#include <cuda_runtime.h>

#define HW 65536
#define NB 4

typedef unsigned long long ull;

// ---------------- scratch (device globals; no runtime allocation) ----------------
__device__ float g_pre [NB * 384 * HW];   // pre-dwconv:  [b][ch384][hw]
__device__ float g_post[NB * 384 * HW];   // post-dwconv: [b][ch384][hw]
// canonical channel order: 0..127 kv1 (k1=0..63, v1=64..127), 128..191 q2,
//                          192..255 q1, 256..383 kv2 (k2=256..319, v2=320..383)
__device__ float g_S  [2 * NB * 8 * 64];  // [(br*4+b)*8+h]*64 + c*8 + d
__device__ float g_sq [2 * NB * 2 * 64];  // [(br*4+b)*2+qk]*64 + ch
__device__ float g_PoF[2 * NB * 64 * 64]; // folded po @ blockdiag(A)

// ---------------- f32x2 helpers ----------------
__device__ __forceinline__ ull pack2(float a) {
    ull r; asm("mov.b64 %0,{%1,%1};" : "=l"(r) : "f"(a)); return r;
}
__device__ __forceinline__ void ffma2(ull& acc, ull a, ull b) {
    asm("fma.rn.f32x2 %0,%1,%2,%0;" : "+l"(acc) : "l"(a), "l"(b));
}
__device__ __forceinline__ float2 unpack2(ull v) {
    float2 f; asm("mov.b64 {%0,%1},%2;" : "=f"(f.x), "=f"(f.y) : "l"(v)); return f;
}

// ---------------- K0: zero stats ----------------
__global__ void k0_zero() {
    int t = blockIdx.x * 256 + threadIdx.x;
    if (t < 2 * NB * 8 * 64) g_S[t] = 0.f;
    if (t < 2 * NB * 2 * 64) g_sq[t] = 0.f;
}

// ---------------- K1: LN + all pointwise (1x1) projections ----------------
// block = 64 consecutive pixels of one image; 384 out channels.
__global__ __launch_bounds__(256, 1) void k1_pointwise(
    const float* __restrict__ x, const float* __restrict__ y,
    const float* __restrict__ lnw, const float* __restrict__ lnb,
    const float* __restrict__ kv1w, const float* __restrict__ q1w,
    const float* __restrict__ kv2w, const float* __restrict__ q2w)
{
    extern __shared__ float sm1[];
    float* Wt = sm1;            // [64k][384oc]
    float* xT = Wt + 24576;     // [64c][66]
    float* yT = xT + 4224;
    float* lw = yT + 4224;      // 64
    float* lb = lw + 64;        // 64

    int tid = threadIdx.x;
    int b   = blockIdx.x >> 10;
    int p0  = (blockIdx.x & 1023) << 6;

    const float* xb = x + (size_t)b * 64 * HW + p0;
    const float* yb = y + (size_t)b * 64 * HW + p0;
    #pragma unroll
    for (int i = 0; i < 16; i++) {
        int idx = tid + i * 256; int c = idx >> 6, p = idx & 63;
        xT[c * 66 + p] = xb[(size_t)c * HW + p];
        yT[c * 66 + p] = yb[(size_t)c * HW + p];
    }
    if (tid < 64) { lw[tid] = lnw[tid]; lb[tid] = lnb[tid]; }
    // weights, transposed to [k][oc'], oc' = canonical order
    #pragma unroll 4
    for (int i = 0; i < 96; i++) {
        int idx = tid + i * 256;
        int k = idx / 384, oc = idx % 384;
        float w;
        if      (oc < 128) w = kv1w[oc * 64 + k];
        else if (oc < 192) w = q2w [(oc - 128) * 64 + k];
        else if (oc < 256) w = q1w [(oc - 192) * 64 + k];
        else               w = kv2w[(oc - 256) * 64 + k];
        Wt[k * 384 + oc] = w;
    }
    __syncthreads();

    // LayerNorm over channels, per pixel (threads 0..63 -> x, 64..127 -> y)
    if (tid < 128) {
        int p = tid & 63;
        float* T = (tid < 64) ? xT : yT;
        float s = 0.f, s2 = 0.f;
        #pragma unroll
        for (int c = 0; c < 64; c++) { float v = T[c * 66 + p]; s += v; s2 += v * v; }
        float mu = s * (1.f / 64.f);
        float var = s2 * (1.f / 64.f) - mu * mu;
        float r = rsqrtf(var + 1e-5f);
        #pragma unroll
        for (int c = 0; c < 64; c++)
            T[c * 66 + p] = (T[c * 66 + p] - mu) * r * lw[c] + lb[c];
    }
    __syncthreads();

    // GEMM: thread = (og, pg); 6 oc x 16 px micro-tile (8 f32x2 pairs)
    int og = tid >> 2, pg = tid & 3;
    int oc0 = og * 6, px0 = pg * 16;
    const float* src = (og < 32) ? xT : yT;   // oc'<192 from x1, else y1
    ull acc[6][8];
    #pragma unroll
    for (int i = 0; i < 6; i++)
        #pragma unroll
        for (int j = 0; j < 8; j++) acc[i][j] = 0ull;

    #pragma unroll 4
    for (int k = 0; k < 64; k++) {
        const ull* srow = (const ull*)(src + k * 66 + px0);
        ull xv[8];
        #pragma unroll
        for (int j = 0; j < 8; j++) xv[j] = srow[j];
        #pragma unroll
        for (int i = 0; i < 6; i++) {
            ull ww = pack2(Wt[k * 384 + oc0 + i]);
            #pragma unroll
            for (int j = 0; j < 8; j++) ffma2(acc[i][j], ww, xv[j]);
        }
    }
    float* outb = g_pre + ((size_t)b * 384) * HW + p0 + px0;
    #pragma unroll
    for (int i = 0; i < 6; i++) {
        ull* orow = (ull*)(outb + (size_t)(oc0 + i) * HW);
        #pragma unroll
        for (int j = 0; j < 8; j++) orow[j] = acc[i][j];
    }
}

// ---------------- K2: depthwise 3x3 conv, zero pad ----------------
__global__ void k2_dwconv(const float* __restrict__ kvdw1, const float* __restrict__ qdw1,
                          const float* __restrict__ kvdw2, const float* __restrict__ qdw2)
{
    int plane = blockIdx.z;          // b*384 + c
    int c = plane % 384;
    const float* w9;
    if      (c < 128) w9 = kvdw1 + c * 9;
    else if (c < 192) w9 = qdw2 + (c - 128) * 9;
    else if (c < 256) w9 = qdw1 + (c - 192) * 9;
    else              w9 = kvdw2 + (c - 256) * 9;
    float w[9];
    #pragma unroll
    for (int i = 0; i < 9; i++) w[i] = __ldg(w9 + i);

    int col = blockIdx.x * 32 + threadIdx.x;
    int row = blockIdx.y * 8 + threadIdx.y;
    const float* in = g_pre + (size_t)plane * HW;
    float s = 0.f;
    #pragma unroll
    for (int dr = -1; dr <= 1; dr++) {
        int r = row + dr;
        if (r < 0 || r > 255) continue;
        #pragma unroll
        for (int dc = -1; dc <= 1; dc++) {
            int cc = col + dc;
            if (cc < 0 || cc > 255) continue;
            s += w[(dr + 1) * 3 + (dc + 1)] * __ldg(in + r * 256 + cc);
        }
    }
    g_post[(size_t)plane * HW + row * 256 + col] = s;
}

// ---------------- K3: attention stats (q.k cross sums + norms) ----------------
__device__ __forceinline__ float warp_red(float v) {
    #pragma unroll
    for (int o = 16; o; o >>= 1) v += __shfl_xor_sync(0xffffffffu, v, o);
    return v;
}
__global__ __launch_bounds__(256, 1) void k3_stats()
{
    int blk = blockIdx.x;            // 4b * 2br * 8h * 32chunk = 2048
    int chunk = blk & 31;
    int h  = (blk >> 5) & 7;
    int br = (blk >> 8) & 1;
    int b  = blk >> 9;
    int qc = (br ? 128 : 192) + h * 8;
    int kc = (br ? 256 :   0) + h * 8;
    const float* qp = g_post + ((size_t)(b * 384 + qc)) * HW + chunk * 2048 + threadIdx.x;
    const float* kp = g_post + ((size_t)(b * 384 + kc)) * HW + chunk * 2048 + threadIdx.x;

    float S[8][8], qs[8], ks[8];
    #pragma unroll
    for (int i = 0; i < 8; i++) {
        qs[i] = 0.f; ks[i] = 0.f;
        #pragma unroll
        for (int j = 0; j < 8; j++) S[i][j] = 0.f;
    }
    for (int it = 0; it < 8; it++) {
        int off = it * 256;
        float qv[8], kv[8];
        #pragma unroll
        for (int i = 0; i < 8; i++) { qv[i] = qp[(size_t)i * HW + off]; kv[i] = kp[(size_t)i * HW + off]; }
        #pragma unroll
        for (int i = 0; i < 8; i++) {
            qs[i] += qv[i] * qv[i];
            ks[i] += kv[i] * kv[i];
            #pragma unroll
            for (int j = 0; j < 8; j++) S[i][j] += qv[i] * kv[j];
        }
    }
    int lane = threadIdx.x & 31;
    size_t sb = ((size_t)(br * 4 + b) * 8 + h) * 64;
    #pragma unroll
    for (int i = 0; i < 8; i++)
        #pragma unroll
        for (int j = 0; j < 8; j++) {
            float v = warp_red(S[i][j]);
            if (!lane) atomicAdd(&g_S[sb + i * 8 + j], v);
        }
    size_t qb = ((size_t)(br * 4 + b) * 2) * 64 + h * 8;
    #pragma unroll
    for (int i = 0; i < 8; i++) {
        float v = warp_red(qs[i]); if (!lane) atomicAdd(&g_sq[qb + i], v);
        v = warp_red(ks[i]);       if (!lane) atomicAdd(&g_sq[qb + 64 + i], v);
    }
}

// ---------------- K4: softmax + fold po @ blockdiag(A) ----------------
__global__ void k4_fold(const float* __restrict__ temp,
                        const float* __restrict__ po1, const float* __restrict__ po2)
{
    int br = blockIdx.x & 1, b = blockIdx.x >> 1;
    __shared__ float A[8][8][8];
    __shared__ float nq[64], nk[64];
    int t = threadIdx.x;  // 0..63
    {
        size_t qb = ((size_t)(br * 4 + b) * 2) * 64;
        nq[t] = fmaxf(sqrtf(g_sq[qb + t]), 1e-12f);
        nk[t] = fmaxf(sqrtf(g_sq[qb + 64 + t]), 1e-12f);
    }
    __syncthreads();
    {
        int h = t >> 3, c = t & 7;
        float tp = temp[h];
        const float* Srow = g_S + ((size_t)(br * 4 + b) * 8 + h) * 64 + c * 8;
        float v[8], mx = -1e30f;
        #pragma unroll
        for (int d = 0; d < 8; d++) {
            v[d] = Srow[d] / (nq[h * 8 + c] * nk[h * 8 + d]) * tp;
            mx = fmaxf(mx, v[d]);
        }
        float sum = 0.f;
        #pragma unroll
        for (int d = 0; d < 8; d++) { v[d] = expf(v[d] - mx); sum += v[d]; }
        float inv = 1.f / sum;
        #pragma unroll
        for (int d = 0; d < 8; d++) A[h][c][d] = v[d] * inv;
    }
    __syncthreads();
    const float* po = br ? po2 : po1;
    for (int hd = 0; hd < 64; hd++) {
        int h = hd >> 3, d = hd & 7;
        float s = 0.f;
        #pragma unroll
        for (int c = 0; c < 8; c++) s += po[t * 64 + h * 8 + c] * A[h][c][d];
        g_PoF[((size_t)(br * 4 + b) * 64 + t) * 64 + hd] = s;
    }
}

// ---------------- K5: modulation MLP + folded projection + residual ----------------
__device__ __forceinline__ void loadW(float* Wsm, float* bsm, const float* __restrict__ g,
                                      const float* __restrict__ gb, int tid)
{
    #pragma unroll
    for (int i = 0; i < 16; i++) {
        int idx = tid + i * 256;
        Wsm[(idx & 63) * 65 + (idx >> 6)] = g[idx];
    }
    if (tid < 64) bsm[tid] = gb ? gb[tid] : 0.f;
}

// MODE 0: lrelu(acc+b) -> dst ; 1: acc+b -> dst ; 2: auxV = auxV*(sT+1)+(acc+b) ;
// MODE 3: gout = acc + res
template <int MODE>
__device__ __forceinline__ void stage64(const float* __restrict__ Wsm, const float* __restrict__ bsm,
                                        const float* __restrict__ src, float* dst,
                                        const float* auxS, float* auxV,
                                        const float* res, float* gout, int tid)
{
    int og = tid >> 3, pg = tid & 7;
    int oc0 = og * 2, px0 = pg * 8;
    ull acc[2][4];
    #pragma unroll
    for (int i = 0; i < 2; i++)
        #pragma unroll
        for (int j = 0; j < 4; j++) acc[i][j] = 0ull;

    #pragma unroll 8
    for (int k = 0; k < 64; k++) {
        const ull* srow = (const ull*)(src + k * 66 + px0);
        ull x0 = srow[0], x1 = srow[1], x2 = srow[2], x3 = srow[3];
        #pragma unroll
        for (int i = 0; i < 2; i++) {
            ull ww = pack2(Wsm[k * 65 + oc0 + i]);
            ffma2(acc[i][0], ww, x0); ffma2(acc[i][1], ww, x1);
            ffma2(acc[i][2], ww, x2); ffma2(acc[i][3], ww, x3);
        }
    }
    #pragma unroll
    for (int i = 0; i < 2; i++) {
        int oc = oc0 + i;
        float bb = (MODE < 3) ? bsm[oc] : 0.f;
        #pragma unroll
        for (int j = 0; j < 4; j++) {
            float2 v = unpack2(acc[i][j]);
            int p = px0 + 2 * j;
            int idx = oc * 66 + p;
            if (MODE == 0) {
                float a = v.x + bb, c2 = v.y + bb;
                dst[idx]     = a  > 0.f ? a  : 0.1f * a;
                dst[idx + 1] = c2 > 0.f ? c2 : 0.1f * c2;
            } else if (MODE == 1) {
                dst[idx] = v.x + bb; dst[idx + 1] = v.y + bb;
            } else if (MODE == 2) {
                auxV[idx]     = auxV[idx]     * (auxS[idx]     + 1.f) + (v.x + bb);
                auxV[idx + 1] = auxV[idx + 1] * (auxS[idx + 1] + 1.f) + (v.y + bb);
            } else {
                gout[(size_t)oc * HW + p]     = v.x + res[idx];
                gout[(size_t)oc * HW + p + 1] = v.y + res[idx + 1];
            }
        }
    }
}

__global__ __launch_bounds__(256, 1) void k5_final(
    const float* __restrict__ x, const float* __restrict__ y,
    const float* __restrict__ mm1w, const float* __restrict__ mm1b,
    const float* __restrict__ mm2w, const float* __restrict__ mm2b,
    float* __restrict__ out)
{
    extern __shared__ float sm5[];
    float* xT  = sm5;
    float* yT  = xT + 4224;
    float* vaT = yT + 4224;
    float* vbT = vaT + 4224;
    float* hT  = vbT + 4224;
    float* sT  = hT + 4224;
    float* Wsm = sT + 4224;   // [64k][65]
    float* bsm = Wsm + 4160;  // 64

    int tid = threadIdx.x;
    int b   = blockIdx.x >> 10;
    int p0  = (blockIdx.x & 1023) << 6;

    const float* xb = x + (size_t)b * 64 * HW + p0;
    const float* yb = y + (size_t)b * 64 * HW + p0;
    const float* va = g_post + ((size_t)b * 384 + 64)  * HW + p0;  // v1
    const float* vb = g_post + ((size_t)b * 384 + 320) * HW + p0;  // v2
    #pragma unroll
    for (int i = 0; i < 16; i++) {
        int idx = tid + i * 256; int c = idx >> 6, p = idx & 63;
        size_t g = (size_t)c * HW + p; int s = c * 66 + p;
        xT[s] = xb[g]; yT[s] = yb[g]; vaT[s] = va[g]; vbT[s] = vb[g];
    }

    float* out1 = out + (size_t)b * 64 * HW + p0;
    float* out2 = out + (size_t)NB * 64 * HW + (size_t)b * 64 * HW + p0;

    // ---- branch 1: modulate v1 by x, project with PoF1, residual y ----
    loadW(Wsm, bsm, mm1w, mm1b, tid);                 __syncthreads();
    stage64<0>(Wsm, bsm, xT, hT, 0, 0, 0, 0, tid);    __syncthreads();
    loadW(Wsm, bsm, mm1w + 4096, mm1b + 64, tid);     __syncthreads();
    stage64<1>(Wsm, bsm, hT, sT, 0, 0, 0, 0, tid);    __syncthreads();
    loadW(Wsm, bsm, mm1w + 8192, mm1b + 128, tid);    __syncthreads();
    stage64<0>(Wsm, bsm, xT, hT, 0, 0, 0, 0, tid);    __syncthreads();
    loadW(Wsm, bsm, mm1w + 12288, mm1b + 192, tid);   __syncthreads();
    stage64<2>(Wsm, bsm, hT, 0, sT, vaT, 0, 0, tid);  __syncthreads();
    loadW(Wsm, bsm, g_PoF + (size_t)b * 4096, 0, tid);          __syncthreads();
    stage64<3>(Wsm, bsm, vaT, 0, 0, 0, yT, out1, tid);          __syncthreads();

    // ---- branch 2: modulate v2 by y, project with PoF2, residual x ----
    loadW(Wsm, bsm, mm2w, mm2b, tid);                 __syncthreads();
    stage64<0>(Wsm, bsm, yT, hT, 0, 0, 0, 0, tid);    __syncthreads();
    loadW(Wsm, bsm, mm2w + 4096, mm2b + 64, tid);     __syncthreads();
    stage64<1>(Wsm, bsm, hT, sT, 0, 0, 0, 0, tid);    __syncthreads();
    loadW(Wsm, bsm, mm2w + 8192, mm2b + 128, tid);    __syncthreads();
    stage64<0>(Wsm, bsm, yT, hT, 0, 0, 0, 0, tid);    __syncthreads();
    loadW(Wsm, bsm, mm2w + 12288, mm2b + 192, tid);   __syncthreads();
    stage64<2>(Wsm, bsm, hT, 0, sT, vbT, 0, 0, tid);  __syncthreads();
    loadW(Wsm, bsm, g_PoF + (size_t)(4 + b) * 4096, 0, tid);    __syncthreads();
    stage64<3>(Wsm, bsm, vbT, 0, 0, 0, xT, out2, tid);
}

// ---------------- launch ----------------
extern "C" void kernel_launch(void* const* d_in, const int* in_sizes, int n_in,
                              void* d_out, int out_size)
{
    const float* x     = (const float*)d_in[0];
    const float* y     = (const float*)d_in[1];
    const float* lnw   = (const float*)d_in[2];
    const float* lnb   = (const float*)d_in[3];
    const float* temp  = (const float*)d_in[4];
    const float* kv1w  = (const float*)d_in[5];
    const float* kvdw1 = (const float*)d_in[6];
    const float* q1w   = (const float*)d_in[7];
    const float* qdw1  = (const float*)d_in[8];
    const float* po1   = (const float*)d_in[9];
    const float* kv2w  = (const float*)d_in[10];
    const float* kvdw2 = (const float*)d_in[11];
    const float* q2w   = (const float*)d_in[12];
    const float* qdw2  = (const float*)d_in[13];
    const float* po2   = (const float*)d_in[14];
    const float* mm1w  = (const float*)d_in[15];
    const float* mm1b  = (const float*)d_in[16];
    const float* mm2w  = (const float*)d_in[17];
    const float* mm2b  = (const float*)d_in[18];
    float* out = (float*)d_out;

    cudaFuncSetAttribute(k1_pointwise, cudaFuncAttributeMaxDynamicSharedMemorySize, 132608);
    cudaFuncSetAttribute(k5_final,     cudaFuncAttributeMaxDynamicSharedMemorySize, 118272);

    k0_zero<<<16, 256>>>();
    k1_pointwise<<<4096, 256, 132608>>>(x, y, lnw, lnb, kv1w, q1w, kv2w, q2w);
    k2_dwconv<<<dim3(8, 32, NB * 384), dim3(32, 8)>>>(kvdw1, qdw1, kvdw2, qdw2);
    k3_stats<<<2048, 256>>>();
    k4_fold<<<8, 64>>>(temp, po1, po2);
    k5_final<<<4096, 256, 118272>>>(x, y, mm1w, mm1b, mm2w, mm2b, out);
}